// round 1
// baseline (speedup 1.0000x reference)
#include <cuda_runtime.h>

// DWT_2D Haar: x [16,64,256,256] f32 -> (LL,LH,HL,HH) each [16,64,128,128]
// Algebraic collapse of the 4-GEMM reference: each band pixel = +-sum of a
// disjoint 2x2 input block * 0.5. Pure streaming kernel.
//
// Shapes (hardcoded per problem):
//   N   = B*C = 1024 images
//   H=W = 256, Lh=Lw = 128
//   input image stride  = 256*256 = 65536 floats
//   band image stride   = 128*128 = 16384 floats
//   band tensor stride  = 1024*16384 = 16777216 floats
//
// Each thread: 4 output cols of one output row of one image.
//   reads  2x float4 from input row 2i, 2x float4 from row 2i+1 (64 B)
//   writes 1x float4 to each of LL,LH,HL,HH (64 B)

static constexpr int NIMG      = 16 * 64;          // 1024
static constexpr int IN_W      = 256;
static constexpr int OUT_W     = 128;
static constexpr int IN_IMG    = 256 * 256;        // 65536
static constexpr int OUT_IMG   = 128 * 128;        // 16384
static constexpr long long BAND_STRIDE = (long long)NIMG * OUT_IMG; // 16777216

__global__ __launch_bounds__(256)
void dwt2d_haar_kernel(const float* __restrict__ x, float* __restrict__ out)
{
    int t = blockIdx.x * blockDim.x + threadIdx.x;
    // t layout: [n (1024)] [i (128)] [j4 (32)]   -> 4,194,304 threads total
    int j4 = t & 31;          // output col group (4 cols each)
    int i  = (t >> 5) & 127;  // output row
    int n  = t >> 12;         // image index

    const float4* __restrict__ r0 =
        reinterpret_cast<const float4*>(x + (long long)n * IN_IMG + (long long)(2 * i)     * IN_W) + (j4 << 1);
    const float4* __restrict__ r1 =
        reinterpret_cast<const float4*>(x + (long long)n * IN_IMG + (long long)(2 * i + 1) * IN_W) + (j4 << 1);

    // 8 input cols -> 4 output cols
    float4 p0 = r0[0];
    float4 p1 = r0[1];
    float4 q0 = r1[0];
    float4 q1 = r1[1];

    // top row pairs (a,b), bottom row pairs (c,d) for 4 output cols
    // col 0: (p0.x,p0.y | q0.x,q0.y)
    // col 1: (p0.z,p0.w | q0.z,q0.w)
    // col 2: (p1.x,p1.y | q1.x,q1.y)
    // col 3: (p1.z,p1.w | q1.z,q1.w)
    float4 ll, lh, hl, hh;

    {
        float a = p0.x, b = p0.y, c = q0.x, d = q0.y;
        ll.x = 0.5f * ((a + b) + (c + d));
        lh.x = 0.5f * ((a - b) + (c - d));
        hl.x = 0.5f * ((a + b) - (c + d));
        hh.x = 0.5f * ((a - b) - (c - d));
    }
    {
        float a = p0.z, b = p0.w, c = q0.z, d = q0.w;
        ll.y = 0.5f * ((a + b) + (c + d));
        lh.y = 0.5f * ((a - b) + (c - d));
        hl.y = 0.5f * ((a + b) - (c + d));
        hh.y = 0.5f * ((a - b) - (c - d));
    }
    {
        float a = p1.x, b = p1.y, c = q1.x, d = q1.y;
        ll.z = 0.5f * ((a + b) + (c + d));
        lh.z = 0.5f * ((a - b) + (c - d));
        hl.z = 0.5f * ((a + b) - (c + d));
        hh.z = 0.5f * ((a - b) - (c - d));
    }
    {
        float a = p1.z, b = p1.w, c = q1.z, d = q1.w;
        ll.w = 0.5f * ((a + b) + (c + d));
        lh.w = 0.5f * ((a - b) + (c - d));
        hl.w = 0.5f * ((a + b) - (c + d));
        hh.w = 0.5f * ((a - b) - (c - d));
    }

    long long obase = (long long)n * OUT_IMG + (long long)i * OUT_W + (j4 << 2);
    float4* __restrict__ o = reinterpret_cast<float4*>(out + obase);
    const long long bs4 = BAND_STRIDE >> 2;   // band stride in float4 units

    float4* __restrict__ o4 = reinterpret_cast<float4*>(out) + (obase >> 2);
    o4[0]       = ll;   // LL
    o4[bs4]     = lh;   // LH
    o4[2 * bs4] = hl;   // HL
    o4[3 * bs4] = hh;   // HH
    (void)o;
}

extern "C" void kernel_launch(void* const* d_in, const int* in_sizes, int n_in,
                              void* d_out, int out_size)
{
    const float* x = (const float*)d_in[0];   // [16,64,256,256] f32
    // d_in[1..4] are the Haar DWT matrices -- algebraically folded, unused.
    float* out = (float*)d_out;               // 4 x [16,64,128,128] f32 concat

    // total threads = 1024 * 128 * 32 = 4,194,304
    int threads = 256;
    int blocks  = (NIMG * 128 * 32) / threads;  // 16384
    dwt2d_haar_kernel<<<blocks, threads>>>(x, out);
}